// round 2
// baseline (speedup 1.0000x reference)
#include <cuda_runtime.h>
#include <cuda_bf16.h>

#define N_NODES 50000
#define N_EDGES 800000
#define F_IN 128
#define HID 256

// Scratch (allocation-free rule: __device__ globals)
__device__ __align__(16) float g_agg[(size_t)N_NODES * HID];
__device__ __align__(16) float g_h1[(size_t)N_NODES * HID];
__device__ __align__(16) float g_cnt[N_NODES];

// ---------------------------------------------------------------------------
// zero
__global__ void k_zero(float* __restrict__ p, int n) {
    int i = blockIdx.x * blockDim.x + threadIdx.x;
    if (i < n) p[i] = 0.0f;
}

// ---------------------------------------------------------------------------
// scatter layer 1: warp per edge, 128 floats, lane handles float4
__global__ void k_scatter1(const float* __restrict__ x, const int* __restrict__ ei) {
    int warp = (blockIdx.x * blockDim.x + threadIdx.x) >> 5;
    int lane = threadIdx.x & 31;
    if (warp >= N_EDGES) return;
    int src = ei[warp];
    int dst = ei[N_EDGES + warp];
    float4 v = ((const float4*)(x + (size_t)src * F_IN))[lane];
    float* a = g_agg + (size_t)dst * F_IN + lane * 4;
    atomicAdd(a + 0, v.x); atomicAdd(a + 1, v.y);
    atomicAdd(a + 2, v.z); atomicAdd(a + 3, v.w);
    if (lane == 0) atomicAdd(&g_cnt[dst], 1.0f);
}

// scatter layer 2: warp per edge, 256 floats, lane handles 2x float4
__global__ void k_scatter2(const float* __restrict__ h1, const int* __restrict__ ei) {
    int warp = (blockIdx.x * blockDim.x + threadIdx.x) >> 5;
    int lane = threadIdx.x & 31;
    if (warp >= N_EDGES) return;
    int src = ei[warp];
    int dst = ei[N_EDGES + warp];
    const float4* hp = (const float4*)(h1 + (size_t)src * HID);
    float4 va = hp[lane];
    float4 vb = hp[lane + 32];
    float* a = g_agg + (size_t)dst * HID;
    float* pa = a + lane * 4;
    float* pb = a + 128 + lane * 4;
    atomicAdd(pa + 0, va.x); atomicAdd(pa + 1, va.y);
    atomicAdd(pa + 2, va.z); atomicAdd(pa + 3, va.w);
    atomicAdd(pb + 0, vb.x); atomicAdd(pb + 1, vb.y);
    atomicAdd(pb + 2, vb.z); atomicAdd(pb + 3, vb.w);
}

// ---------------------------------------------------------------------------
// normalize: agg[node, :] /= max(cnt[node], 1)
__global__ void k_norm(float* __restrict__ agg, const float* __restrict__ cnt,
                       int feat4, int total4) {
    int i = blockIdx.x * blockDim.x + threadIdx.x;
    if (i >= total4) return;
    int node = i / feat4;
    float s = 1.0f / fmaxf(cnt[node], 1.0f);
    float4 v = ((float4*)agg)[i];
    v.x *= s; v.y *= s; v.z *= s; v.w *= s;
    ((float4*)agg)[i] = v;
}

// ---------------------------------------------------------------------------
// Fused double-GEMM: C[n,256] = act(A1 @ W1^T + A2 @ W2^T + bias)
// W1/W2: [256, K] row-major. BM=64, BN=256, BK=32, 256 threads, 4x16 per thread.
template <int K, bool RELU>
__global__ __launch_bounds__(256) void k_gemm2(
    const float* __restrict__ A1, const float* __restrict__ W1,
    const float* __restrict__ A2, const float* __restrict__ W2,
    const float* __restrict__ bias, float* __restrict__ C, int nrows) {
    constexpr int BM = 64;
    constexpr int BK = 32;
    constexpr int LDT = 36;  // padded stride (floats), multiple of 4

    extern __shared__ float sm[];
    float* Ws1 = sm;                    // 256 * 36
    float* Ws2 = Ws1 + 256 * LDT;       // 256 * 36
    float* As1 = Ws2 + 256 * LDT;       // 64 * 36
    float* As2 = As1 + BM * LDT;        // 64 * 36

    int tid = threadIdx.x;
    int tx = tid & 15;   // col lane: handles cols j*16 + tx
    int ty = tid >> 4;   // row group: handles rows ty*4 .. ty*4+3
    int row0 = blockIdx.x * BM;

    float acc[4][16];
#pragma unroll
    for (int r = 0; r < 4; ++r)
#pragma unroll
        for (int j = 0; j < 16; ++j) acc[r][j] = 0.0f;

    for (int k0 = 0; k0 < K; k0 += BK) {
        // load W tiles: 256 rows x 32 k (8 float4 each)
#pragma unroll
        for (int jj = 0; jj < 8; ++jj) {
            int i = tid + 256 * jj;
            int c = i >> 3, kq = i & 7;
            float4 w1 = *(const float4*)(W1 + (size_t)c * K + k0 + kq * 4);
            float4 w2 = *(const float4*)(W2 + (size_t)c * K + k0 + kq * 4);
            *(float4*)(Ws1 + c * LDT + kq * 4) = w1;
            *(float4*)(Ws2 + c * LDT + kq * 4) = w2;
        }
        // load A tiles: 64 rows x 32 k
#pragma unroll
        for (int jj = 0; jj < 2; ++jj) {
            int i = tid + 256 * jj;
            int r = i >> 3, kq = i & 7;
            int row = row0 + r;
            float4 a1 = make_float4(0.f, 0.f, 0.f, 0.f);
            float4 a2 = make_float4(0.f, 0.f, 0.f, 0.f);
            if (row < nrows) {
                a1 = *(const float4*)(A1 + (size_t)row * K + k0 + kq * 4);
                a2 = *(const float4*)(A2 + (size_t)row * K + k0 + kq * 4);
            }
            *(float4*)(As1 + r * LDT + kq * 4) = a1;
            *(float4*)(As2 + r * LDT + kq * 4) = a2;
        }
        __syncthreads();

#pragma unroll
        for (int kq = 0; kq < 8; ++kq) {
            float4 a1[4], a2[4];
#pragma unroll
            for (int r = 0; r < 4; ++r) {
                a1[r] = *(float4*)(As1 + (ty * 4 + r) * LDT + kq * 4);
                a2[r] = *(float4*)(As2 + (ty * 4 + r) * LDT + kq * 4);
            }
#pragma unroll
            for (int j = 0; j < 16; ++j) {
                int c = j * 16 + tx;
                float4 w1 = *(float4*)(Ws1 + c * LDT + kq * 4);
                float4 w2 = *(float4*)(Ws2 + c * LDT + kq * 4);
#pragma unroll
                for (int r = 0; r < 4; ++r) {
                    acc[r][j] += a1[r].x * w1.x + a1[r].y * w1.y +
                                 a1[r].z * w1.z + a1[r].w * w1.w +
                                 a2[r].x * w2.x + a2[r].y * w2.y +
                                 a2[r].z * w2.z + a2[r].w * w2.w;
                }
            }
        }
        __syncthreads();
    }

#pragma unroll
    for (int r = 0; r < 4; ++r) {
        int row = row0 + ty * 4 + r;
        if (row >= nrows) continue;
#pragma unroll
        for (int j = 0; j < 16; ++j) {
            int c = j * 16 + tx;
            float v = acc[r][j] + bias[c];
            if (RELU) v = fmaxf(v, 0.0f);
            C[(size_t)row * 256 + c] = v;
        }
    }
}

// ---------------------------------------------------------------------------
// heads: warp per node, 7 dot products of length 256
__global__ void k_heads(const float* __restrict__ h,
                        const float* __restrict__ Wh1, const float* __restrict__ bh1,
                        const float* __restrict__ Wh2, const float* __restrict__ bh2,
                        float* __restrict__ out1, float* __restrict__ out2) {
    int warp = (blockIdx.x * blockDim.x + threadIdx.x) >> 5;
    int lane = threadIdx.x & 31;
    if (warp >= N_NODES) return;
    const float4* hp = (const float4*)(h + (size_t)warp * HID);
    float4 v0 = hp[lane * 2];
    float4 v1 = hp[lane * 2 + 1];
#pragma unroll
    for (int o = 0; o < 7; ++o) {
        const float* w = (o < 4) ? (Wh1 + (size_t)o * HID) : (Wh2 + (size_t)(o - 4) * HID);
        float4 w0 = ((const float4*)w)[lane * 2];
        float4 w1 = ((const float4*)w)[lane * 2 + 1];
        float p = v0.x * w0.x + v0.y * w0.y + v0.z * w0.z + v0.w * w0.w +
                  v1.x * w1.x + v1.y * w1.y + v1.z * w1.z + v1.w * w1.w;
#pragma unroll
        for (int s = 16; s > 0; s >>= 1) p += __shfl_xor_sync(0xFFFFFFFFu, p, s);
        if (lane == 0) {
            if (o < 4) out1[(size_t)warp * 4 + o] = p + bh1[o];
            else       out2[(size_t)warp * 3 + (o - 4)] = p + bh2[o - 4];
        }
    }
}

// ---------------------------------------------------------------------------
extern "C" void kernel_launch(void* const* d_in, const int* in_sizes, int n_in,
                              void* d_out, int out_size) {
    const float* x   = (const float*)d_in[0];
    const int*   ei  = (const int*)d_in[1];
    const float* W1l = (const float*)d_in[2];
    const float* b1l = (const float*)d_in[3];
    const float* W1r = (const float*)d_in[4];
    const float* W2l = (const float*)d_in[5];
    const float* b2l = (const float*)d_in[6];
    const float* W2r = (const float*)d_in[7];
    const float* Wh1 = (const float*)d_in[8];
    const float* bh1 = (const float*)d_in[9];
    const float* Wh2 = (const float*)d_in[10];
    const float* bh2 = (const float*)d_in[11];

    float* out  = (float*)d_out;
    float* out1 = out;                       // [N, 4]
    float* out2 = out + (size_t)N_NODES * 4; // [N, 3]
    float* hout = out + (size_t)N_NODES * 7; // [N, 256]

    float *agg, *h1, *cnt;
    cudaGetSymbolAddress((void**)&agg, g_agg);
    cudaGetSymbolAddress((void**)&h1, g_h1);
    cudaGetSymbolAddress((void**)&cnt, g_cnt);

    const size_t smem = (size_t)(2 * 256 * 36 + 2 * 64 * 36) * sizeof(float);
    cudaFuncSetAttribute(k_gemm2<F_IN, true>, cudaFuncAttributeMaxDynamicSharedMemorySize, (int)smem);
    cudaFuncSetAttribute(k_gemm2<HID, false>, cudaFuncAttributeMaxDynamicSharedMemorySize, (int)smem);

    const int TB = 256;
    const int scatter_blocks = (N_EDGES * 32 + TB - 1) / TB;
    const int gemm_blocks = (N_NODES + 63) / 64;

    // ---- layer 1 ----
    {
        int n = N_NODES * F_IN;
        k_zero<<<(n + TB - 1) / TB, TB>>>(agg, n);
        k_zero<<<(N_NODES + TB - 1) / TB, TB>>>(cnt, N_NODES);
    }
    k_scatter1<<<scatter_blocks, TB>>>(x, ei);
    {
        int total4 = N_NODES * (F_IN / 4);
        k_norm<<<(total4 + TB - 1) / TB, TB>>>(agg, cnt, F_IN / 4, total4);
    }
    k_gemm2<F_IN, true><<<gemm_blocks, TB, smem>>>(agg, W1l, x, W1r, b1l, h1, N_NODES);

    // ---- layer 2 (cnt is identical, reuse) ----
    {
        int n = N_NODES * HID;
        k_zero<<<(n + TB - 1) / TB, TB>>>(agg, n);
    }
    k_scatter2<<<scatter_blocks, TB>>>(h1, ei);
    {
        int total4 = N_NODES * (HID / 4);
        k_norm<<<(total4 + TB - 1) / TB, TB>>>(agg, cnt, HID / 4, total4);
    }
    k_gemm2<HID, false><<<gemm_blocks, TB, smem>>>(agg, W2l, h1, W2r, b2l, hout, N_NODES);

    // ---- heads ----
    k_heads<<<(N_NODES * 32 + TB - 1) / TB, TB>>>(hout, Wh1, bh1, Wh2, bh2, out1, out2);
}

// round 5
// speedup vs baseline: 1.1076x; 1.1076x over previous
#include <cuda_runtime.h>
#include <cuda_bf16.h>

#define N_NODES 50000
#define N_EDGES 800000
#define F_IN 128
#define HID 256

// Scratch (allocation-free rule: __device__ globals)
__device__ __align__(16) float g_agg[(size_t)N_NODES * HID];
__device__ __align__(16) float g_h1[(size_t)N_NODES * HID];
__device__ int g_deg[N_NODES];
__device__ int g_off[N_NODES + 1];
__device__ int g_cur[N_NODES];
__device__ int g_srcs[N_EDGES];

// ---------------------------------------------------------------------------
__global__ void k_zero_int(int* __restrict__ p, int n) {
    int i = blockIdx.x * blockDim.x + threadIdx.x;
    if (i < n) p[i] = 0;
}

// histogram of dst
__global__ void k_hist(const int* __restrict__ ei) {
    int e = blockIdx.x * blockDim.x + threadIdx.x;
    if (e >= N_EDGES) return;
    atomicAdd(&g_deg[ei[N_EDGES + e]], 1);
}

// exclusive scan of g_deg -> g_off (single block, 1024 threads)
__global__ __launch_bounds__(1024) void k_scan() {
    __shared__ int ssum[1024];
    const int CH = (N_NODES + 1023) / 1024;
    int tid = threadIdx.x;
    int base = tid * CH;
    int s = 0;
    for (int i = 0; i < CH; ++i) {
        int idx = base + i;
        if (idx < N_NODES) s += g_deg[idx];
    }
    ssum[tid] = s;
    __syncthreads();
    // Hillis-Steele inclusive scan
    for (int d = 1; d < 1024; d <<= 1) {
        int v = (tid >= d) ? ssum[tid - d] : 0;
        __syncthreads();
        ssum[tid] += v;
        __syncthreads();
    }
    int run = (tid == 0) ? 0 : ssum[tid - 1];
    for (int i = 0; i < CH; ++i) {
        int idx = base + i;
        if (idx < N_NODES) {
            g_off[idx] = run;
            g_cur[idx] = run;
            run += g_deg[idx];
        }
    }
    if (tid == 1023) g_off[N_NODES] = N_EDGES;
}

// bucket-fill: src list sorted by dst
__global__ void k_fill(const int* __restrict__ ei) {
    int e = blockIdx.x * blockDim.x + threadIdx.x;
    if (e >= N_EDGES) return;
    int src = ei[e];
    int dst = ei[N_EDGES + e];
    int pos = atomicAdd(&g_cur[dst], 1);
    g_srcs[pos] = src;
}

// ---------------------------------------------------------------------------
// gather-mean, F=128: warp per node, lane holds one float4 of the row
__global__ void k_agg1(const float* __restrict__ x) {
    int node = (blockIdx.x * blockDim.x + threadIdx.x) >> 5;
    int lane = threadIdx.x & 31;
    if (node >= N_NODES) return;
    int beg = g_off[node], end = g_off[node + 1];
    float4 acc = make_float4(0.f, 0.f, 0.f, 0.f);
    for (int e = beg; e < end; ++e) {
        int s = g_srcs[e];
        float4 v = ((const float4*)(x + (size_t)s * F_IN))[lane];
        acc.x += v.x; acc.y += v.y; acc.z += v.z; acc.w += v.w;
    }
    float inv = (end > beg) ? 1.0f / (float)(end - beg) : 0.0f;
    acc.x *= inv; acc.y *= inv; acc.z *= inv; acc.w *= inv;
    ((float4*)(g_agg + (size_t)node * F_IN))[lane] = acc;
}

// gather-mean, F=256: warp per node, lane holds two float4s
__global__ void k_agg2(const float* __restrict__ h1) {
    int node = (blockIdx.x * blockDim.x + threadIdx.x) >> 5;
    int lane = threadIdx.x & 31;
    if (node >= N_NODES) return;
    int beg = g_off[node], end = g_off[node + 1];
    float4 a0 = make_float4(0.f, 0.f, 0.f, 0.f);
    float4 a1 = make_float4(0.f, 0.f, 0.f, 0.f);
    for (int e = beg; e < end; ++e) {
        int s = g_srcs[e];
        const float4* hp = (const float4*)(h1 + (size_t)s * HID);
        float4 v0 = hp[lane];
        float4 v1 = hp[lane + 32];
        a0.x += v0.x; a0.y += v0.y; a0.z += v0.z; a0.w += v0.w;
        a1.x += v1.x; a1.y += v1.y; a1.z += v1.z; a1.w += v1.w;
    }
    float inv = (end > beg) ? 1.0f / (float)(end - beg) : 0.0f;
    a0.x *= inv; a0.y *= inv; a0.z *= inv; a0.w *= inv;
    a1.x *= inv; a1.y *= inv; a1.z *= inv; a1.w *= inv;
    float4* ap = (float4*)(g_agg + (size_t)node * HID);
    ap[lane] = a0;
    ap[lane + 32] = a1;
}

// ---------------------------------------------------------------------------
// Fused double-GEMM: C[n,256] = act(A1 @ W1^T + A2 @ W2^T + bias)
// W1/W2: [256, K] row-major. BM=64, BN=256, BK=32, 256 threads, 4x16 per thread.
template <int K, bool RELU>
__global__ __launch_bounds__(256) void k_gemm2(
    const float* __restrict__ A1, const float* __restrict__ W1,
    const float* __restrict__ A2, const float* __restrict__ W2,
    const float* __restrict__ bias, float* __restrict__ C, int nrows) {
    constexpr int BM = 64;
    constexpr int BK = 32;
    constexpr int LDT = 36;

    extern __shared__ float sm[];
    float* Ws1 = sm;
    float* Ws2 = Ws1 + 256 * LDT;
    float* As1 = Ws2 + 256 * LDT;
    float* As2 = As1 + BM * LDT;

    int tid = threadIdx.x;
    int tx = tid & 15;
    int ty = tid >> 4;
    int row0 = blockIdx.x * BM;

    float acc[4][16];
#pragma unroll
    for (int r = 0; r < 4; ++r)
#pragma unroll
        for (int j = 0; j < 16; ++j) acc[r][j] = 0.0f;

    for (int k0 = 0; k0 < K; k0 += BK) {
#pragma unroll
        for (int jj = 0; jj < 8; ++jj) {
            int i = tid + 256 * jj;
            int c = i >> 3, kq = i & 7;
            float4 w1 = *(const float4*)(W1 + (size_t)c * K + k0 + kq * 4);
            float4 w2 = *(const float4*)(W2 + (size_t)c * K + k0 + kq * 4);
            *(float4*)(Ws1 + c * LDT + kq * 4) = w1;
            *(float4*)(Ws2 + c * LDT + kq * 4) = w2;
        }
#pragma unroll
        for (int jj = 0; jj < 2; ++jj) {
            int i = tid + 256 * jj;
            int r = i >> 3, kq = i & 7;
            int row = row0 + r;
            float4 a1 = make_float4(0.f, 0.f, 0.f, 0.f);
            float4 a2 = make_float4(0.f, 0.f, 0.f, 0.f);
            if (row < nrows) {
                a1 = *(const float4*)(A1 + (size_t)row * K + k0 + kq * 4);
                a2 = *(const float4*)(A2 + (size_t)row * K + k0 + kq * 4);
            }
            *(float4*)(As1 + r * LDT + kq * 4) = a1;
            *(float4*)(As2 + r * LDT + kq * 4) = a2;
        }
        __syncthreads();

#pragma unroll
        for (int kq = 0; kq < 8; ++kq) {
            float4 a1[4], a2[4];
#pragma unroll
            for (int r = 0; r < 4; ++r) {
                a1[r] = *(float4*)(As1 + (ty * 4 + r) * LDT + kq * 4);
                a2[r] = *(float4*)(As2 + (ty * 4 + r) * LDT + kq * 4);
            }
#pragma unroll
            for (int j = 0; j < 16; ++j) {
                int c = j * 16 + tx;
                float4 w1 = *(float4*)(Ws1 + c * LDT + kq * 4);
                float4 w2 = *(float4*)(Ws2 + c * LDT + kq * 4);
#pragma unroll
                for (int r = 0; r < 4; ++r) {
                    acc[r][j] += a1[r].x * w1.x + a1[r].y * w1.y +
                                 a1[r].z * w1.z + a1[r].w * w1.w +
                                 a2[r].x * w2.x + a2[r].y * w2.y +
                                 a2[r].z * w2.z + a2[r].w * w2.w;
                }
            }
        }
        __syncthreads();
    }

#pragma unroll
    for (int r = 0; r < 4; ++r) {
        int row = row0 + ty * 4 + r;
        if (row >= nrows) continue;
#pragma unroll
        for (int j = 0; j < 16; ++j) {
            int c = j * 16 + tx;
            float v = acc[r][j] + bias[c];
            if (RELU) v = fmaxf(v, 0.0f);
            C[(size_t)row * 256 + c] = v;
        }
    }
}

// ---------------------------------------------------------------------------
// heads: warp per node, 7 dot products of length 256
__global__ void k_heads(const float* __restrict__ h,
                        const float* __restrict__ Wh1, const float* __restrict__ bh1,
                        const float* __restrict__ Wh2, const float* __restrict__ bh2,
                        float* __restrict__ out1, float* __restrict__ out2) {
    int warp = (blockIdx.x * blockDim.x + threadIdx.x) >> 5;
    int lane = threadIdx.x & 31;
    if (warp >= N_NODES) return;
    const float4* hp = (const float4*)(h + (size_t)warp * HID);
    float4 v0 = hp[lane * 2];
    float4 v1 = hp[lane * 2 + 1];
#pragma unroll
    for (int o = 0; o < 7; ++o) {
        const float* w = (o < 4) ? (Wh1 + (size_t)o * HID) : (Wh2 + (size_t)(o - 4) * HID);
        float4 w0 = ((const float4*)w)[lane * 2];
        float4 w1 = ((const float4*)w)[lane * 2 + 1];
        float p = v0.x * w0.x + v0.y * w0.y + v0.z * w0.z + v0.w * w0.w +
                  v1.x * w1.x + v1.y * w1.y + v1.z * w1.z + v1.w * w1.w;
#pragma unroll
        for (int s = 16; s > 0; s >>= 1) p += __shfl_xor_sync(0xFFFFFFFFu, p, s);
        if (lane == 0) {
            if (o < 4) out1[(size_t)warp * 4 + o] = p + bh1[o];
            else       out2[(size_t)warp * 3 + (o - 4)] = p + bh2[o - 4];
        }
    }
}

// ---------------------------------------------------------------------------
extern "C" void kernel_launch(void* const* d_in, const int* in_sizes, int n_in,
                              void* d_out, int out_size) {
    const float* x   = (const float*)d_in[0];
    const int*   ei  = (const int*)d_in[1];
    const float* W1l = (const float*)d_in[2];
    const float* b1l = (const float*)d_in[3];
    const float* W1r = (const float*)d_in[4];
    const float* W2l = (const float*)d_in[5];
    const float* b2l = (const float*)d_in[6];
    const float* W2r = (const float*)d_in[7];
    const float* Wh1 = (const float*)d_in[8];
    const float* bh1 = (const float*)d_in[9];
    const float* Wh2 = (const float*)d_in[10];
    const float* bh2 = (const float*)d_in[11];

    float* out  = (float*)d_out;
    float* out1 = out;
    float* out2 = out + (size_t)N_NODES * 4;
    float* hout = out + (size_t)N_NODES * 7;

    float *agg, *h1;
    int *deg;
    cudaGetSymbolAddress((void**)&agg, g_agg);
    cudaGetSymbolAddress((void**)&h1, g_h1);
    cudaGetSymbolAddress((void**)&deg, g_deg);

    const size_t smem = (size_t)(2 * 256 * 36 + 2 * 64 * 36) * sizeof(float);
    cudaFuncSetAttribute(k_gemm2<F_IN, true>, cudaFuncAttributeMaxDynamicSharedMemorySize, (int)smem);
    cudaFuncSetAttribute(k_gemm2<HID, false>, cudaFuncAttributeMaxDynamicSharedMemorySize, (int)smem);

    const int TB = 256;
    const int edge_blocks = (N_EDGES + TB - 1) / TB;
    const int node_warp_blocks = (N_NODES * 32 + TB - 1) / TB;
    const int gemm_blocks = (N_NODES + 63) / 64;

    // ---- CSR build (shared by both layers) ----
    k_zero_int<<<(N_NODES + TB - 1) / TB, TB>>>(deg, N_NODES);
    k_hist<<<edge_blocks, TB>>>(ei);
    k_scan<<<1, 1024>>>();
    k_fill<<<edge_blocks, TB>>>(ei);

    // ---- layer 1 ----
    k_agg1<<<node_warp_blocks, TB>>>(x);
    k_gemm2<F_IN, true><<<gemm_blocks, TB, smem>>>(agg, W1l, x, W1r, b1l, h1, N_NODES);

    // ---- layer 2 ----
    k_agg2<<<node_warp_blocks, TB>>>(h1);
    k_gemm2<HID, false><<<gemm_blocks, TB, smem>>>(agg, W2l, h1, W2r, b2l, hout, N_NODES);

    // ---- heads ----
    k_heads<<<node_warp_blocks, TB>>>(hout, Wh1, bh1, Wh2, bh2, out1, out2);
}

// round 6
// speedup vs baseline: 2.3683x; 2.1382x over previous
#include <cuda_runtime.h>
#include <cuda_bf16.h>
#include <stdint.h>

#define N_NODES 50000
#define N_EDGES 800000
#define F_IN 128
#define HID 256

// Scratch (allocation-free rule: __device__ globals)
__device__ __align__(16) float g_agg[(size_t)N_NODES * HID];
__device__ __align__(16) float g_h1[(size_t)N_NODES * HID];
__device__ int g_deg[N_NODES];
__device__ int g_off[N_NODES + 1];
__device__ int g_cur[N_NODES];
__device__ int g_srcs[N_EDGES];

// bf16 hi/lo split weights
__device__ __align__(16) __nv_bfloat16 g_w1l_h[256 * 128];
__device__ __align__(16) __nv_bfloat16 g_w1l_l[256 * 128];
__device__ __align__(16) __nv_bfloat16 g_w1r_h[256 * 128];
__device__ __align__(16) __nv_bfloat16 g_w1r_l[256 * 128];
__device__ __align__(16) __nv_bfloat16 g_w2l_h[256 * 256];
__device__ __align__(16) __nv_bfloat16 g_w2l_l[256 * 256];
__device__ __align__(16) __nv_bfloat16 g_w2r_h[256 * 256];
__device__ __align__(16) __nv_bfloat16 g_w2r_l[256 * 256];

// ---------------------------------------------------------------------------
__global__ void k_zero_int(int* __restrict__ p, int n) {
    int i = blockIdx.x * blockDim.x + threadIdx.x;
    if (i < n) p[i] = 0;
}

__global__ void k_hist(const int* __restrict__ ei) {
    int e = blockIdx.x * blockDim.x + threadIdx.x;
    if (e >= N_EDGES) return;
    atomicAdd(&g_deg[ei[N_EDGES + e]], 1);
}

__global__ __launch_bounds__(1024) void k_scan() {
    __shared__ int ssum[1024];
    const int CH = (N_NODES + 1023) / 1024;
    int tid = threadIdx.x;
    int base = tid * CH;
    int s = 0;
    for (int i = 0; i < CH; ++i) {
        int idx = base + i;
        if (idx < N_NODES) s += g_deg[idx];
    }
    ssum[tid] = s;
    __syncthreads();
    for (int d = 1; d < 1024; d <<= 1) {
        int v = (tid >= d) ? ssum[tid - d] : 0;
        __syncthreads();
        ssum[tid] += v;
        __syncthreads();
    }
    int run = (tid == 0) ? 0 : ssum[tid - 1];
    for (int i = 0; i < CH; ++i) {
        int idx = base + i;
        if (idx < N_NODES) {
            g_off[idx] = run;
            g_cur[idx] = run;
            run += g_deg[idx];
        }
    }
    if (tid == 1023) g_off[N_NODES] = N_EDGES;
}

__global__ void k_fill(const int* __restrict__ ei) {
    int e = blockIdx.x * blockDim.x + threadIdx.x;
    if (e >= N_EDGES) return;
    int src = ei[e];
    int dst = ei[N_EDGES + e];
    int pos = atomicAdd(&g_cur[dst], 1);
    g_srcs[pos] = src;
}

// ---------------------------------------------------------------------------
// weight split: hi = bf16(v), lo = bf16(v - hi)
__global__ void k_wconv(const float* __restrict__ src, __nv_bfloat16* __restrict__ hi,
                        __nv_bfloat16* __restrict__ lo, int n) {
    int i = blockIdx.x * blockDim.x + threadIdx.x;
    if (i >= n) return;
    float v = src[i];
    __nv_bfloat16 h = __float2bfloat16(v);
    hi[i] = h;
    lo[i] = __float2bfloat16(v - __bfloat162float(h));
}

// ---------------------------------------------------------------------------
// gather-mean, F=128: warp per node, 4x unrolled for MLP
__global__ void k_agg1(const float* __restrict__ x) {
    int node = (blockIdx.x * blockDim.x + threadIdx.x) >> 5;
    int lane = threadIdx.x & 31;
    if (node >= N_NODES) return;
    int beg = g_off[node], end = g_off[node + 1];
    float4 acc = make_float4(0.f, 0.f, 0.f, 0.f);
    int e = beg;
    for (; e + 4 <= end; e += 4) {
        int s0 = g_srcs[e], s1 = g_srcs[e + 1], s2 = g_srcs[e + 2], s3 = g_srcs[e + 3];
        float4 v0 = ((const float4*)(x + (size_t)s0 * F_IN))[lane];
        float4 v1 = ((const float4*)(x + (size_t)s1 * F_IN))[lane];
        float4 v2 = ((const float4*)(x + (size_t)s2 * F_IN))[lane];
        float4 v3 = ((const float4*)(x + (size_t)s3 * F_IN))[lane];
        acc.x += v0.x + v1.x + v2.x + v3.x;
        acc.y += v0.y + v1.y + v2.y + v3.y;
        acc.z += v0.z + v1.z + v2.z + v3.z;
        acc.w += v0.w + v1.w + v2.w + v3.w;
    }
    for (; e < end; ++e) {
        int s = g_srcs[e];
        float4 v = ((const float4*)(x + (size_t)s * F_IN))[lane];
        acc.x += v.x; acc.y += v.y; acc.z += v.z; acc.w += v.w;
    }
    float inv = (end > beg) ? 1.0f / (float)(end - beg) : 0.0f;
    acc.x *= inv; acc.y *= inv; acc.z *= inv; acc.w *= inv;
    ((float4*)(g_agg + (size_t)node * F_IN))[lane] = acc;
}

// gather-mean, F=256: warp per node, 2x unrolled (4 outstanding float4s)
__global__ void k_agg2(const float* __restrict__ h1) {
    int node = (blockIdx.x * blockDim.x + threadIdx.x) >> 5;
    int lane = threadIdx.x & 31;
    if (node >= N_NODES) return;
    int beg = g_off[node], end = g_off[node + 1];
    float4 a0 = make_float4(0.f, 0.f, 0.f, 0.f);
    float4 a1 = make_float4(0.f, 0.f, 0.f, 0.f);
    int e = beg;
    for (; e + 2 <= end; e += 2) {
        int s0 = g_srcs[e], s1 = g_srcs[e + 1];
        const float4* p0 = (const float4*)(h1 + (size_t)s0 * HID);
        const float4* p1 = (const float4*)(h1 + (size_t)s1 * HID);
        float4 v0a = p0[lane], v0b = p0[lane + 32];
        float4 v1a = p1[lane], v1b = p1[lane + 32];
        a0.x += v0a.x + v1a.x; a0.y += v0a.y + v1a.y;
        a0.z += v0a.z + v1a.z; a0.w += v0a.w + v1a.w;
        a1.x += v0b.x + v1b.x; a1.y += v0b.y + v1b.y;
        a1.z += v0b.z + v1b.z; a1.w += v0b.w + v1b.w;
    }
    for (; e < end; ++e) {
        int s = g_srcs[e];
        const float4* hp = (const float4*)(h1 + (size_t)s * HID);
        float4 v0 = hp[lane], v1 = hp[lane + 32];
        a0.x += v0.x; a0.y += v0.y; a0.z += v0.z; a0.w += v0.w;
        a1.x += v1.x; a1.y += v1.y; a1.z += v1.z; a1.w += v1.w;
    }
    float inv = (end > beg) ? 1.0f / (float)(end - beg) : 0.0f;
    a0.x *= inv; a0.y *= inv; a0.z *= inv; a0.w *= inv;
    a1.x *= inv; a1.y *= inv; a1.z *= inv; a1.w *= inv;
    float4* ap = (float4*)(g_agg + (size_t)node * HID);
    ap[lane] = a0;
    ap[lane + 32] = a1;
}

// ---------------------------------------------------------------------------
// Tensor-core fused double-GEMM (bf16x3 split, fp32 accum):
//   C[n,256] = act(A1 @ W1^T + A2 @ W2^T + bias)
// BM=128, BN=128, BK=32, 256 threads (8 warps), warp tile 32x64.
#define MMA_BF16(d, a, b)                                                     \
    asm volatile(                                                             \
        "mma.sync.aligned.m16n8k16.row.col.f32.bf16.bf16.f32 "                \
        "{%0,%1,%2,%3}, {%4,%5,%6,%7}, {%8,%9}, {%0,%1,%2,%3};"               \
        : "+f"((d)[0]), "+f"((d)[1]), "+f"((d)[2]), "+f"((d)[3])              \
        : "r"((a)[0]), "r"((a)[1]), "r"((a)[2]), "r"((a)[3]),                 \
          "r"((b)[0]), "r"((b)[1]))

template <int K, bool RELU>
__global__ __launch_bounds__(256) void k_gemm_tc(
    const float* __restrict__ A1, const __nv_bfloat16* __restrict__ W1h,
    const __nv_bfloat16* __restrict__ W1lo,
    const float* __restrict__ A2, const __nv_bfloat16* __restrict__ W2h,
    const __nv_bfloat16* __restrict__ W2lo,
    const float* __restrict__ bias, float* __restrict__ C, int nrows) {
    constexpr int LD = 40;  // bf16 units; frag loads hit 32 distinct banks
    __shared__ __nv_bfloat16 sAh[128 * LD];
    __shared__ __nv_bfloat16 sAl[128 * LD];
    __shared__ __nv_bfloat16 sBh[128 * LD];
    __shared__ __nv_bfloat16 sBl[128 * LD];

    int tid = threadIdx.x;
    int wid = tid >> 5, lane = tid & 31;
    int g = lane >> 2, t = lane & 3;
    int warp_m = wid & 3;   // 4 warps over 128 rows (32 each)
    int warp_n = wid >> 2;  // 2 warps over 128 cols (64 each)
    int row0 = blockIdx.x * 128, col0 = blockIdx.y * 128;

    float acc[2][8][4];
#pragma unroll
    for (int mt = 0; mt < 2; ++mt)
#pragma unroll
        for (int nt = 0; nt < 8; ++nt)
#pragma unroll
            for (int c = 0; c < 4; ++c) acc[mt][nt][c] = 0.0f;

#pragma unroll
    for (int seg = 0; seg < 2; ++seg) {
        const float* A = seg ? A2 : A1;
        const __nv_bfloat16* Wh = seg ? W2h : W1h;
        const __nv_bfloat16* Wl = seg ? W2lo : W1lo;
        for (int k0 = 0; k0 < K; k0 += 32) {
            // stage A: fp32 -> hi/lo bf16 in smem
#pragma unroll
            for (int i = 0; i < 4; ++i) {
                int idx = tid + 256 * i;          // 0..1023
                int r = idx >> 3, kq = idx & 7;   // r:0..127, k=4*kq
                float4 v = make_float4(0.f, 0.f, 0.f, 0.f);
                int row = row0 + r;
                if (row < nrows) v = *(const float4*)(A + (size_t)row * K + k0 + 4 * kq);
                __nv_bfloat16 hx = __float2bfloat16(v.x);
                __nv_bfloat16 hy = __float2bfloat16(v.y);
                __nv_bfloat16 hz = __float2bfloat16(v.z);
                __nv_bfloat16 hw = __float2bfloat16(v.w);
                __nv_bfloat16 lx = __float2bfloat16(v.x - __bfloat162float(hx));
                __nv_bfloat16 ly = __float2bfloat16(v.y - __bfloat162float(hy));
                __nv_bfloat16 lz = __float2bfloat16(v.z - __bfloat162float(hz));
                __nv_bfloat16 lw = __float2bfloat16(v.w - __bfloat162float(hw));
                __nv_bfloat162* dh = (__nv_bfloat162*)&sAh[r * LD + 4 * kq];
                __nv_bfloat162* dl = (__nv_bfloat162*)&sAl[r * LD + 4 * kq];
                dh[0] = __halves2bfloat162(hx, hy);
                dh[1] = __halves2bfloat162(hz, hw);
                dl[0] = __halves2bfloat162(lx, ly);
                dl[1] = __halves2bfloat162(lz, lw);
            }
            // stage B (W rows col0..col0+127): preconverted bf16 hi/lo
#pragma unroll
            for (int i = 0; i < 8; ++i) {
                int idx = tid + 256 * i;           // 0..2047
                int r = idx >> 4, kq = idx & 15;   // r:0..127, k=2*kq
                size_t gidx = (size_t)(col0 + r) * K + k0 + 2 * kq;
                *(uint32_t*)&sBh[r * LD + 2 * kq] = *(const uint32_t*)(Wh + gidx);
                *(uint32_t*)&sBl[r * LD + 2 * kq] = *(const uint32_t*)(Wl + gidx);
            }
            __syncthreads();

#pragma unroll
            for (int ks = 0; ks < 2; ++ks) {
                int kb = ks * 16;
                uint32_t ah[2][4], al[2][4];
#pragma unroll
                for (int mt = 0; mt < 2; ++mt) {
                    int mr = warp_m * 32 + mt * 16;
                    int o0 = (mr + g) * LD + kb + 2 * t;
                    int o1 = (mr + g + 8) * LD + kb + 2 * t;
                    ah[mt][0] = *(uint32_t*)&sAh[o0];
                    ah[mt][1] = *(uint32_t*)&sAh[o1];
                    ah[mt][2] = *(uint32_t*)&sAh[o0 + 8];
                    ah[mt][3] = *(uint32_t*)&sAh[o1 + 8];
                    al[mt][0] = *(uint32_t*)&sAl[o0];
                    al[mt][1] = *(uint32_t*)&sAl[o1];
                    al[mt][2] = *(uint32_t*)&sAl[o0 + 8];
                    al[mt][3] = *(uint32_t*)&sAl[o1 + 8];
                }
                uint32_t bh[8][2], bl[8][2];
#pragma unroll
                for (int nt = 0; nt < 8; ++nt) {
                    int nr = warp_n * 64 + nt * 8;
                    int o = (nr + g) * LD + kb + 2 * t;
                    bh[nt][0] = *(uint32_t*)&sBh[o];
                    bh[nt][1] = *(uint32_t*)&sBh[o + 8];
                    bl[nt][0] = *(uint32_t*)&sBl[o];
                    bl[nt][1] = *(uint32_t*)&sBl[o + 8];
                }
#pragma unroll
                for (int mt = 0; mt < 2; ++mt)
#pragma unroll
                    for (int nt = 0; nt < 8; ++nt) {
                        MMA_BF16(acc[mt][nt], ah[mt], bh[nt]);
                        MMA_BF16(acc[mt][nt], ah[mt], bl[nt]);
                        MMA_BF16(acc[mt][nt], al[mt], bh[nt]);
                    }
            }
            __syncthreads();
        }
    }

    // epilogue
#pragma unroll
    for (int mt = 0; mt < 2; ++mt) {
#pragma unroll
        for (int nt = 0; nt < 8; ++nt) {
            int col = col0 + warp_n * 64 + nt * 8 + 2 * t;
            float b0 = bias[col], b1 = bias[col + 1];
            int r0 = row0 + warp_m * 32 + mt * 16 + g;
            if (r0 < nrows) {
                float v0 = acc[mt][nt][0] + b0;
                float v1 = acc[mt][nt][1] + b1;
                if (RELU) { v0 = fmaxf(v0, 0.f); v1 = fmaxf(v1, 0.f); }
                C[(size_t)r0 * 256 + col] = v0;
                C[(size_t)r0 * 256 + col + 1] = v1;
            }
            int r1 = r0 + 8;
            if (r1 < nrows) {
                float v2 = acc[mt][nt][2] + b0;
                float v3 = acc[mt][nt][3] + b1;
                if (RELU) { v2 = fmaxf(v2, 0.f); v3 = fmaxf(v3, 0.f); }
                C[(size_t)r1 * 256 + col] = v2;
                C[(size_t)r1 * 256 + col + 1] = v3;
            }
        }
    }
}

// ---------------------------------------------------------------------------
// heads: warp per node, 7 dot products of length 256
__global__ void k_heads(const float* __restrict__ h,
                        const float* __restrict__ Wh1, const float* __restrict__ bh1,
                        const float* __restrict__ Wh2, const float* __restrict__ bh2,
                        float* __restrict__ out1, float* __restrict__ out2) {
    int warp = (blockIdx.x * blockDim.x + threadIdx.x) >> 5;
    int lane = threadIdx.x & 31;
    if (warp >= N_NODES) return;
    const float4* hp = (const float4*)(h + (size_t)warp * HID);
    float4 v0 = hp[lane * 2];
    float4 v1 = hp[lane * 2 + 1];
#pragma unroll
    for (int o = 0; o < 7; ++o) {
        const float* w = (o < 4) ? (Wh1 + (size_t)o * HID) : (Wh2 + (size_t)(o - 4) * HID);
        float4 w0 = ((const float4*)w)[lane * 2];
        float4 w1 = ((const float4*)w)[lane * 2 + 1];
        float p = v0.x * w0.x + v0.y * w0.y + v0.z * w0.z + v0.w * w0.w +
                  v1.x * w1.x + v1.y * w1.y + v1.z * w1.z + v1.w * w1.w;
#pragma unroll
        for (int s = 16; s > 0; s >>= 1) p += __shfl_xor_sync(0xFFFFFFFFu, p, s);
        if (lane == 0) {
            if (o < 4) out1[(size_t)warp * 4 + o] = p + bh1[o];
            else       out2[(size_t)warp * 3 + (o - 4)] = p + bh2[o - 4];
        }
    }
}

// ---------------------------------------------------------------------------
extern "C" void kernel_launch(void* const* d_in, const int* in_sizes, int n_in,
                              void* d_out, int out_size) {
    const float* x   = (const float*)d_in[0];
    const int*   ei  = (const int*)d_in[1];
    const float* W1l = (const float*)d_in[2];
    const float* b1l = (const float*)d_in[3];
    const float* W1r = (const float*)d_in[4];
    const float* W2l = (const float*)d_in[5];
    const float* b2l = (const float*)d_in[6];
    const float* W2r = (const float*)d_in[7];
    const float* Wh1 = (const float*)d_in[8];
    const float* bh1 = (const float*)d_in[9];
    const float* Wh2 = (const float*)d_in[10];
    const float* bh2 = (const float*)d_in[11];

    float* out  = (float*)d_out;
    float* out1 = out;
    float* out2 = out + (size_t)N_NODES * 4;
    float* hout = out + (size_t)N_NODES * 7;

    float *agg, *h1;
    int *deg;
    cudaGetSymbolAddress((void**)&agg, g_agg);
    cudaGetSymbolAddress((void**)&h1, g_h1);
    cudaGetSymbolAddress((void**)&deg, g_deg);

    __nv_bfloat16 *w1lh, *w1ll, *w1rh, *w1rl, *w2lh, *w2ll, *w2rh, *w2rl;
    cudaGetSymbolAddress((void**)&w1lh, g_w1l_h);
    cudaGetSymbolAddress((void**)&w1ll, g_w1l_l);
    cudaGetSymbolAddress((void**)&w1rh, g_w1r_h);
    cudaGetSymbolAddress((void**)&w1rl, g_w1r_l);
    cudaGetSymbolAddress((void**)&w2lh, g_w2l_h);
    cudaGetSymbolAddress((void**)&w2ll, g_w2l_l);
    cudaGetSymbolAddress((void**)&w2rh, g_w2r_h);
    cudaGetSymbolAddress((void**)&w2rl, g_w2r_l);

    const int TB = 256;
    const int edge_blocks = (N_EDGES + TB - 1) / TB;
    const int node_warp_blocks = (N_NODES * 32 + TB - 1) / TB;
    dim3 gemm_grid((N_NODES + 127) / 128, 2);

    // ---- weight split (tiny) ----
    k_wconv<<<(256 * 128 + TB - 1) / TB, TB>>>(W1l, w1lh, w1ll, 256 * 128);
    k_wconv<<<(256 * 128 + TB - 1) / TB, TB>>>(W1r, w1rh, w1rl, 256 * 128);
    k_wconv<<<(256 * 256 + TB - 1) / TB, TB>>>(W2l, w2lh, w2ll, 256 * 256);
    k_wconv<<<(256 * 256 + TB - 1) / TB, TB>>>(W2r, w2rh, w2rl, 256 * 256);

    // ---- CSR build (shared by both layers) ----
    k_zero_int<<<(N_NODES + TB - 1) / TB, TB>>>(deg, N_NODES);
    k_hist<<<edge_blocks, TB>>>(ei);
    k_scan<<<1, 1024>>>();
    k_fill<<<edge_blocks, TB>>>(ei);

    // ---- layer 1 ----
    k_agg1<<<node_warp_blocks, TB>>>(x);
    k_gemm_tc<F_IN, true><<<gemm_grid, TB>>>(agg, w1lh, w1ll, x, w1rh, w1rl, b1l, h1, N_NODES);

    // ---- layer 2 ----
    k_agg2<<<node_warp_blocks, TB>>>(h1);
    k_gemm_tc<HID, false><<<gemm_grid, TB>>>(agg, w2lh, w2ll, h1, w2rh, w2rl, b2l, hout, N_NODES);

    // ---- heads ----
    k_heads<<<node_warp_blocks, TB>>>(hout, Wh1, bh1, Wh2, bh2, out1, out2);
}